// round 3
// baseline (speedup 1.0000x reference)
#include <cuda_runtime.h>
#include <cuda_bf16.h>
#include <math.h>

// UnitarySpectralFilter: psi [4096,4096,4] f32, alpha scalar f32.
// Analytic 4-point FFT -> unitary phase filter -> IFFT, collapsed to a
// linear map per length-4 vector:
//   S = x0+x1+x2+x3 (DC), D = x0-x1+x2-x3 (Nyquist), A = x0-x2, B = x3-x1
//   y = combos of S*e^{i p0}/4, D*e^{i p2}/4, (A|B)*e^{i p1}/2
// Output layout decided at runtime from out_size:
//   out_size == 2*psi_elems -> interleaved complex (re,im) float pairs
//   out_size ==   psi_elems -> real part only (float32)

static constexpr unsigned NVEC = 4096u * 4096u;   // number of length-4 vectors
static constexpr int THREADS = 256;
static constexpr int VEC_PER_THREAD = 2;
static constexpr unsigned BLOCKS = NVEC / (THREADS * VEC_PER_THREAD);

__device__ __forceinline__ void filter_coeffs(const float* __restrict__ alpha_p,
                                              float kc[6])
{
    const float EPS = 1e-8f;
    float alpha = *alpha_p;
    // fftfreq(4) = [0, .25, -.5, -.25]; |k|+eps = [eps, .25+eps, .5+eps, .25+eps]
    float p0 = alpha * atanf(logf(EPS));
    float p1 = alpha * atanf(logf(0.25f + EPS));
    float p2 = alpha * atanf(logf(0.5f + EPS));
    float c0, s0, c1, s1, c2, s2;
    sincosf(p0, &s0, &c0);
    sincosf(p1, &s1, &c1);
    sincosf(p2, &s2, &c2);
    kc[0] = 0.25f * c0;  kc[1] = 0.25f * s0;   // DC (X0)
    kc[2] = 0.50f * c1;  kc[3] = 0.50f * s1;   // +/-1/4 pair, factor 2 folded
    kc[4] = 0.25f * c2;  kc[5] = 0.25f * s2;   // Nyquist (X2)
}

template <bool COMPLEX_OUT>
__global__ void __launch_bounds__(THREADS)
usf_kernel(const float4* __restrict__ in,
           const float* __restrict__ alpha_p,
           float4* __restrict__ out)
{
    __shared__ float kc[6];
    if (threadIdx.x == 0) filter_coeffs(alpha_p, kc);
    __syncthreads();

    const float k0r = kc[0], k0i = kc[1];
    const float k1r = kc[2], k1i = kc[3];
    const float k2r = kc[4], k2i = kc[5];

    unsigned base = blockIdx.x * (unsigned)(THREADS * VEC_PER_THREAD) + threadIdx.x;

    float4 x[VEC_PER_THREAD];
#pragma unroll
    for (int j = 0; j < VEC_PER_THREAD; j++)
        x[j] = in[base + j * THREADS];

#pragma unroll
    for (int j = 0; j < VEC_PER_THREAD; j++) {
        unsigned idx = base + j * THREADS;
        float x0 = x[j].x, x1 = x[j].y, x2 = x[j].z, x3 = x[j].w;

        float e02 = x0 + x2, e13 = x1 + x3;
        float S = e02 + e13;          // X[0]
        float D = e02 - e13;          // X[2]
        float A = x0 - x2;            // Re X[1]
        float B = x3 - x1;            // Im X[1]

        float t0r = S * k0r, t0i = S * k0i;
        float t2r = D * k2r, t2i = D * k2i;
        float Er = t0r + t2r, Ei = t0i + t2i;   // even outputs base
        float Or = t0r - t2r, Oi = t0i - t2i;   // odd outputs base
        float ar = A * k1r, ai = A * k1i;
        float br = B * k1r, bi = B * k1i;

        if (COMPLEX_OUT) {
            // (y0.re, y0.im, y1.re, y1.im), then (y2.re, y2.im, y3.re, y3.im)
            out[2u * idx]     = make_float4(Er + ar, Ei + ai, Or - br, Oi - bi);
            out[2u * idx + 1] = make_float4(Er - ar, Ei - ai, Or + br, Oi + bi);
        } else {
            // real parts only: (y0, y1, y2, y3)
            out[idx] = make_float4(Er + ar, Or - br, Er - ar, Or + br);
        }
    }
}

extern "C" void kernel_launch(void* const* d_in, const int* in_sizes, int n_in,
                              void* d_out, int out_size)
{
    // psi = largest input, alpha = smallest (robust to scalar size 0 or 1
    // and to metadata ordering).
    int psi_i = 0, alpha_i = 0;
    for (int i = 1; i < n_in; i++) {
        if (in_sizes[i] > in_sizes[psi_i])   psi_i = i;
        if (in_sizes[i] < in_sizes[alpha_i]) alpha_i = i;
    }
    const float4* psi   = (const float4*)d_in[psi_i];
    const float*  alpha = (const float*)d_in[alpha_i];
    float4*       out   = (float4*)d_out;

    long long psi_elems = (long long)in_sizes[psi_i];   // 67,108,864 floats

    if ((long long)out_size >= 2 * psi_elems) {
        // output buffer holds interleaved complex (re,im) float pairs
        usf_kernel<true><<<BLOCKS, THREADS>>>(psi, alpha, out);
    } else {
        // output buffer holds float32 real parts only
        usf_kernel<false><<<BLOCKS, THREADS>>>(psi, alpha, out);
    }
}